// round 13
// baseline (speedup 1.0000x reference)
#include <cuda_runtime.h>
#include <math.h>

#define BB 256
#define SS 256
#define HH 512
#define INF 512
#define XROW 514   // IN + 2
#define NBLK 128
#define KC 64
#define NCHUNK (HH / KC)   // 8

// SMEM: ws (natural f32, 32KB) | A 2x64KB | Gs 32KB = 192KB
#define SM_WS    0
#define SM_AS    32768
#define SM_GS    (32768 + 131072)
#define SM_TOTAL (32768 + 131072 + 32768)   // 196608

// Scratch (device globals; no runtime allocation allowed)
__device__ __align__(128) float g_G[(size_t)SS * 8 * BB * HH]; // [s][gate][b][h]
__device__ __align__(128) float g_hT[2][HH * BB];              // [h][b], ping-pong
__device__ __align__(128) float g_c[HH * BB];                  // cell state [h][b]

// ---- fast activations (HW MUFU; ~1e-6 err vs 1e-3 tolerance) ----
__device__ __forceinline__ float sigf(float x) {
    return __fdividef(1.0f, 1.0f + __expf(-x));
}
__device__ __forceinline__ float tanh_fast(float x) {
    float a = fabsf(x);
    float e = __expf(-2.0f * a);
    float t = __fdividef(1.0f - e, 1.0f + e);
    return copysignf(t, x);
}

// ---- f32x2 packed-FMA helpers ----
__device__ __forceinline__ unsigned long long pk2(float x, float y) {
    unsigned long long r;
    asm("mov.b64 %0, {%1, %2};" : "=l"(r) : "f"(x), "f"(y));
    return r;
}
__device__ __forceinline__ void fma2(unsigned long long& d, unsigned long long a,
                                     unsigned long long b) {
    asm("fma.rn.f32x2 %0, %1, %2, %0;" : "+l"(d) : "l"(a), "l"(b));
}
__device__ __forceinline__ float2 upk2(unsigned long long v) {
    float2 f;
    asm("mov.b64 {%0, %1}, %2;" : "=f"(f.x), "=f"(f.y) : "l"(v));
    return f;
}

// ---- cp.async helpers (cg = L2-only) ----
__device__ __forceinline__ void cpa16(void* dst_smem, const void* src) {
    unsigned d = (unsigned)__cvta_generic_to_shared(dst_smem);
    asm volatile("cp.async.cg.shared.global [%0], [%1], 16;" :: "r"(d), "l"(src));
}
#define CP_COMMIT() asm volatile("cp.async.commit_group;" ::: "memory")
#define CP_WAIT(n)  asm volatile("cp.async.wait_group %0;" :: "n"(n) : "memory")

struct ProjArgs {
    const float* x;
    const float* Wx[8];
    const float* bias[8];
    const float* aux1[8];
    const float* aux2[8];
};

// ---------------------------------------------------------------------------
// Projection GEMM — R3's measured-best version, verbatim.
// ---------------------------------------------------------------------------
__global__ void proj_kernel(ProjArgs p) {
    const int g  = blockIdx.z;
    const int m0 = blockIdx.y * 64;
    const int n0 = blockIdx.x * 64;

    __shared__ float As[64][17];
    __shared__ __align__(16) float Bs[16][64];

    const int tid = threadIdx.x;
    const int tm = tid >> 4;
    const int tn = tid & 15;

    const float* W = p.Wx[g];

    unsigned long long acc2[4][2];
    #pragma unroll
    for (int i = 0; i < 4; i++) { acc2[i][0] = 0ULL; acc2[i][1] = 0ULL; }

    for (int k0 = 0; k0 < INF; k0 += 16) {
        #pragma unroll
        for (int q = 0; q < 4; q++) {
            int m = q * 16 + (tid >> 4);
            int kk = tid & 15;
            As[m][kk] = p.x[(size_t)(m0 + m) * XROW + 2 + k0 + kk];
        }
        {
            int idx = tid * 4;
            int kk = idx >> 6;
            int hc = idx & 63;
            float4 w = *(const float4*)&W[(size_t)(k0 + kk) * HH + n0 + hc];
            *(float4*)&Bs[kk][hc] = w;
        }
        __syncthreads();

        #pragma unroll
        for (int kk = 0; kk < 16; kk++) {
            ulonglong2 bq = *(const ulonglong2*)&Bs[kk][tn * 4];
            #pragma unroll
            for (int i = 0; i < 4; i++) {
                float a = As[tm * 4 + i][kk];
                unsigned long long a2 = pk2(a, a);
                fma2(acc2[i][0], a2, bq.x);
                fma2(acc2[i][1], a2, bq.y);
            }
        }
        __syncthreads();
    }

    const float* bias = p.bias[g];
    const float* a1p = p.aux1[g];
    const float* a2p = p.aux2[g];

    #pragma unroll
    for (int i = 0; i < 4; i++) {
        int m = m0 + tm * 4 + i;
        int bidx = m / SS;
        int sidx = m % SS;
        float Tt = p.x[(size_t)m * XROW + 0];
        float Dt = p.x[(size_t)m * XROW + 1];
        size_t base = (((size_t)sidx * 8 + g) * BB + bidx) * HH;
        float2 lo = upk2(acc2[i][0]);
        float2 hi = upk2(acc2[i][1]);
        float av[4] = {lo.x, lo.y, hi.x, hi.y};
        #pragma unroll
        for (int j = 0; j < 4; j++) {
            int h = n0 + tn * 4 + j;
            float v = av[j] + bias[h];
            if (g == 3 || g == 4)       v += sigf(Tt * a1p[h]);
            else if (g == 5 || g == 6)  v += sigf(Dt * a1p[h]);
            else if (g == 7)            v += Tt * a1p[h] + Dt * a2p[h];
            g_G[base + h] = v;
        }
    }
}

// ---------------------------------------------------------------------------
// LAUNCHED per-step kernel, redesigned body.
// 128 blocks x 512 threads (4 warps/SMSP). Block owns h-cols [h0,h0+4) x 4
// gates. Thread = (1 h, 4 gates packed as 2 col-pairs, 2 b):
//   per k: LDS.64 (a, natural) + 2 movs (dup) + LDS.128 (w, natural
//   gate-interleaved pairs) + 4 FFMA2  -> 6 return wavefronts/warp-k
//   (vs 12 before), small 8-reg acc for deep unroll pipelining.
// Weights stored NATURAL as ws[k][hc][(i,f),(c,o)] (32KB, halved preload).
// ---------------------------------------------------------------------------
__global__ void __launch_bounds__(512, 1)
step_kernel(const float* __restrict__ Whi, const float* __restrict__ Whf,
            const float* __restrict__ Whc, const float* __restrict__ Who,
            float* __restrict__ out, unsigned long long out_size, int t) {
    extern __shared__ __align__(16) char smem_raw[];
    float* wsf   = (float*)(smem_raw + SM_WS);   // [k][hc][g: i,f,c,o]
    float* Asmem = (float*)(smem_raw + SM_AS);   // 2 x [KC][256]
    float* Gs    = (float*)(smem_raw + SM_GS);   // [g][b][4h]

    const int tid = threadIdx.x;
    const int h0 = blockIdx.x * 4;
    const int hc = tid & 3;
    const int b0 = (tid >> 2) * 2;

    const float* hT = g_hT[t & 1];
    float* hTn = g_hT[(t + 1) & 1];

    // G slices first (oldest group; needed only in epilogue)
    {
        #pragma unroll
        for (int i = 0; i < 4; i++) {
            int idx = i * 512 + tid;
            int g = idx >> 8, b = idx & 255;
            const float* srcg = g_G + (((size_t)t * 8 + g) * BB + b) * HH + h0;
            cpa16(Gs + (size_t)idx * 4, srcg);
        }
        CP_COMMIT();
    }
    if (t > 0) {   // chunk 0 of h
        #pragma unroll
        for (int i = 0; i < 8; i++) {
            int off = (i * 512 + tid) * 16;
            cpa16((char*)Asmem + off, (const char*)hT + off);
        }
        CP_COMMIT();
    }

    // Weight preload: natural f32, gate-interleaved (i,f,c,o) per (k,hc).
    if (t > 0) {
        #pragma unroll
        for (int it = 0; it < 4; it++) {
            int idx = it * 512 + tid;          // (k, hc)
            int k = idx >> 2, hcc = idx & 3;
            float4 wv;
            wv.x = __ldg(&Whi[(size_t)k * HH + h0 + hcc]);
            wv.y = __ldg(&Whf[(size_t)k * HH + h0 + hcc]);
            wv.z = __ldg(&Whc[(size_t)k * HH + h0 + hcc]);
            wv.w = __ldg(&Who[(size_t)k * HH + h0 + hcc]);
            *(float4*)&wsf[(size_t)idx * 4] = wv;
        }
    }

    // cell state: (h0+hc, b0..b0+1)
    float cst[2] = {0.f, 0.f};
    if (t > 0) {
        float2 cv = __ldcg((const float2*)&g_c[(h0 + hc) * BB + b0]);
        cst[0] = cv.x; cst[1] = cv.y;
    }

    // acc[pair][b]: pair0=(i,f), pair1=(c,o)
    unsigned long long accIF[2] = {0ULL, 0ULL};
    unsigned long long accCO[2] = {0ULL, 0ULL};

    if (t > 0) {
        for (int c = 0; c < NCHUNK; c++) {
            if (c < NCHUNK - 1) {
                const char* src = (const char*)hT + (size_t)(c + 1) * (KC * 256 * 4);
                char* dst = (char*)Asmem + (size_t)((c + 1) & 1) * (KC * 256 * 4);
                #pragma unroll
                for (int i = 0; i < 8; i++) {
                    int off = (i * 512 + tid) * 16;
                    cpa16(dst + off, src + off);
                }
                CP_COMMIT();
                CP_WAIT(1);
            } else {
                CP_WAIT(0);
            }
            __syncthreads();

            const float* A = Asmem + (size_t)(c & 1) * (KC * 256) + b0;
            const float* wp = wsf + ((size_t)c * KC * 4 + hc) * 4;
            #pragma unroll 8
            for (int k = 0; k < KC; k++) {
                float2 av = *(const float2*)(A + k * 256);
                ulonglong2 w = *(const ulonglong2*)(wp + (size_t)k * 16);
                unsigned long long a0 = pk2(av.x, av.x);
                unsigned long long a1 = pk2(av.y, av.y);
                fma2(accIF[0], a0, w.x);
                fma2(accCO[0], a0, w.y);
                fma2(accIF[1], a1, w.x);
                fma2(accCO[1], a1, w.y);
            }
            __syncthreads();
        }
    } else {
        CP_WAIT(0);
        __syncthreads();
    }

    float hn[2];
    #pragma unroll
    for (int r = 0; r < 2; r++) {
        int b = b0 + r;
        float2 yif = upk2(accIF[r]);
        float2 yco = upk2(accCO[r]);
        float xi = Gs[(0 * 256 + b) * 4 + hc] + yif.x;
        float xf = Gs[(1 * 256 + b) * 4 + hc] + yif.y;
        float xc = Gs[(2 * 256 + b) * 4 + hc] + yco.x;
        float t1 = Gs[(3 * 256 + b) * 4 + hc];
        float t2 = Gs[(4 * 256 + b) * 4 + hc];
        float d1 = Gs[(5 * 256 + b) * 4 + hc];
        float d2 = Gs[(6 * 256 + b) * 4 + hc];
        float o  = Gs[(7 * 256 + b) * 4 + hc] + yco.y;

        float it = sigf(xi);
        float ft = sigf(xf);
        float jj = tanh_fast(xc);
        float T1 = sigf(t1), T2 = sigf(t2), D1 = sigf(d1), D2 = sigf(d2);
        float fc = ft * cst[r];
        float ij = it * jj;
        float chat = fc + ij * T1 * D1;
        float cnew = fc + ij * T2 * D2;
        float ot = sigf(o);
        hn[r] = ot * tanh_fast(chat);
        cst[r] = cnew;
    }

    // next-step hidden + cell state: [h][b] layout, float2 over b
    *(float2*)&hTn[(h0 + hc) * BB + b0] = make_float2(hn[0], hn[1]);
    *(float2*)&g_c[(h0 + hc) * BB + b0] = make_float2(cst[0], cst[1]);

    // stage hn (and c at last step) so 256 threads emit ONE STG.128 each
    float* hs = Asmem;
    float* cs = Asmem + 4096;
    #pragma unroll
    for (int r = 0; r < 2; r++) hs[(b0 + r) * 4 + hc] = hn[r];
    if (t == SS - 1) {
        #pragma unroll
        for (int r = 0; r < 2; r++) cs[(b0 + r) * 4 + hc] = cst[r];
    }
    __syncthreads();
    if (tid < BB) {
        float4 v = *(const float4*)&hs[tid * 4];
        *(float4*)&out[((size_t)tid * SS + t) * HH + h0] = v;
        if (t == SS - 1) {
            unsigned long long base = (unsigned long long)BB * SS * HH;
            unsigned long long o1 = base + (unsigned long long)tid * HH + h0;
            unsigned long long o2 = o1 + (unsigned long long)BB * HH;
            if (o1 + 4 <= out_size) *(float4*)&out[o1] = v;
            if (o2 + 4 <= out_size) *(float4*)&out[o2] = *(const float4*)&cs[tid * 4];
        }
    }
}

extern "C" void kernel_launch(void* const* d_in, const int* in_sizes, int n_in,
                              void* d_out, int out_size) {
    const float* x = (const float*)d_in[0];

    ProjArgs pa = {};
    pa.x = x;
    pa.Wx[0] = (const float*)d_in[1];  pa.bias[0] = (const float*)d_in[3];
    pa.Wx[1] = (const float*)d_in[4];  pa.bias[1] = (const float*)d_in[6];
    pa.Wx[2] = (const float*)d_in[7];  pa.bias[2] = (const float*)d_in[9];
    pa.Wx[3] = (const float*)d_in[10]; pa.aux1[3] = (const float*)d_in[11]; pa.bias[3] = (const float*)d_in[12];
    pa.Wx[4] = (const float*)d_in[13]; pa.aux1[4] = (const float*)d_in[14]; pa.bias[4] = (const float*)d_in[15];
    pa.Wx[5] = (const float*)d_in[16]; pa.aux1[5] = (const float*)d_in[17]; pa.bias[5] = (const float*)d_in[18];
    pa.Wx[6] = (const float*)d_in[19]; pa.aux1[6] = (const float*)d_in[20]; pa.bias[6] = (const float*)d_in[21];
    pa.Wx[7] = (const float*)d_in[22]; pa.aux1[7] = (const float*)d_in[24]; pa.aux2[7] = (const float*)d_in[25];
    pa.bias[7] = (const float*)d_in[26];

    const float* Whi = (const float*)d_in[2];
    const float* Whf = (const float*)d_in[5];
    const float* Whc = (const float*)d_in[8];
    const float* Who = (const float*)d_in[23];

    float* out = (float*)d_out;

    cudaFuncSetAttribute(step_kernel, cudaFuncAttributeMaxDynamicSharedMemorySize,
                         SM_TOTAL);

    dim3 pgrid(HH / 64, (BB * SS) / 64, 8);
    proj_kernel<<<pgrid, 256>>>(pa);

    for (int t = 0; t < SS; t++) {
        step_kernel<<<NBLK, 512, SM_TOTAL>>>(Whi, Whf, Whc, Who, out,
                                             (unsigned long long)out_size, t);
    }
}

// round 17
// speedup vs baseline: 1.1981x; 1.1981x over previous
#include <cuda_runtime.h>
#include <math.h>

#define BB 256
#define SS 256
#define HH 512
#define INF 512
#define XROW 514   // IN + 2
#define NBLK 128
#define KC 64
#define NCHUNK (HH / KC)       // 8
#define CHB (KC * BB * 4)      // 65536 bytes per h chunk
#define WSB (HH * 16 * 4)      // 32768 bytes of interleaved weights per block

// SMEM: ws 32KB | A 2x64KB | Gs 32KB | mbar = 196672
#define SM_WS    0
#define SM_AS    32768
#define SM_GS    (32768 + 131072)
#define SM_MB    (32768 + 131072 + 32768)
#define SM_TOTAL (32768 + 131072 + 32768 + 64)

// Scratch (device globals; no runtime allocation allowed)
__device__ __align__(128) float g_G[(size_t)SS * 8 * BB * HH]; // [s][gate][b][h]
__device__ __align__(128) float g_hT[2][HH * BB];              // [h][b], ping-pong
__device__ __align__(128) float g_c[HH * BB];                  // cell state [h][b]
__device__ __align__(128) float g_Wint[(size_t)NBLK * HH * 16];// [hblk][k][hc][g]

// ---- fast activations (HW MUFU; ~1e-6 err vs 1e-3 tolerance) ----
__device__ __forceinline__ float sigf(float x) {
    return __fdividef(1.0f, 1.0f + __expf(-x));
}
__device__ __forceinline__ float tanh_fast(float x) {
    float a = fabsf(x);
    float e = __expf(-2.0f * a);
    float t = __fdividef(1.0f - e, 1.0f + e);
    return copysignf(t, x);
}

// ---- f32x2 packed-FMA helpers ----
__device__ __forceinline__ unsigned long long pk2(float x, float y) {
    unsigned long long r;
    asm("mov.b64 %0, {%1, %2};" : "=l"(r) : "f"(x), "f"(y));
    return r;
}
__device__ __forceinline__ void fma2(unsigned long long& d, unsigned long long a,
                                     unsigned long long b) {
    asm("fma.rn.f32x2 %0, %1, %2, %0;" : "+l"(d) : "l"(a), "l"(b));
}
__device__ __forceinline__ float2 upk2(unsigned long long v) {
    float2 f;
    asm("mov.b64 {%0, %1}, %2;" : "=f"(f.x), "=f"(f.y) : "l"(v));
    return f;
}

// ---- cp.async (small, for G) ----
__device__ __forceinline__ void cpa16(void* dst_smem, const void* src) {
    unsigned d = (unsigned)__cvta_generic_to_shared(dst_smem);
    asm volatile("cp.async.cg.shared.global [%0], [%1], 16;" :: "r"(d), "l"(src));
}
#define CP_COMMIT() asm volatile("cp.async.commit_group;" ::: "memory")
#define CP_WAIT(n)  asm volatile("cp.async.wait_group %0;" :: "n"(n) : "memory")

// ---- bulk copy + mbarrier ----
__device__ __forceinline__ unsigned smem_u32(const void* p) {
    return (unsigned)__cvta_generic_to_shared(p);
}
__device__ __forceinline__ void mbar_init(unsigned mbar, unsigned cnt) {
    asm volatile("mbarrier.init.shared.b64 [%0], %1;" :: "r"(mbar), "r"(cnt) : "memory");
}
__device__ __forceinline__ void mbar_expect_tx(unsigned mbar, unsigned bytes) {
    asm volatile("mbarrier.arrive.expect_tx.shared.b64 _, [%0], %1;"
                 :: "r"(mbar), "r"(bytes) : "memory");
}
__device__ __forceinline__ void bulk_g2s(unsigned dst_smem, const void* src,
                                         unsigned bytes, unsigned mbar) {
    asm volatile(
        "cp.async.bulk.shared::cluster.global.mbarrier::complete_tx::bytes "
        "[%0], [%1], %2, [%3];"
        :: "r"(dst_smem), "l"(src), "r"(bytes), "r"(mbar) : "memory");
}
__device__ __forceinline__ void mbar_wait(unsigned mbar, unsigned parity) {
    asm volatile(
        "{\n\t.reg .pred P;\n\t"
        "WL_%=:\n\t"
        "mbarrier.try_wait.parity.acquire.cta.shared::cta.b64 P, [%0], %1, 0x989680;\n\t"
        "@P bra WD_%=;\n\t"
        "bra.uni WL_%=;\n\t"
        "WD_%=:\n\t}"
        :: "r"(mbar), "r"(parity) : "memory");
}

struct ProjArgs {
    const float* x;
    const float* Wx[8];
    const float* bias[8];
    const float* aux1[8];
    const float* aux2[8];
};

// ---------------------------------------------------------------------------
// Projection GEMM — R3's measured-best version, verbatim.
// ---------------------------------------------------------------------------
__global__ void proj_kernel(ProjArgs p) {
    const int g  = blockIdx.z;
    const int m0 = blockIdx.y * 64;
    const int n0 = blockIdx.x * 64;

    __shared__ float As[64][17];
    __shared__ __align__(16) float Bs[16][64];

    const int tid = threadIdx.x;
    const int tm = tid >> 4;
    const int tn = tid & 15;

    const float* W = p.Wx[g];

    unsigned long long acc2[4][2];
    #pragma unroll
    for (int i = 0; i < 4; i++) { acc2[i][0] = 0ULL; acc2[i][1] = 0ULL; }

    for (int k0 = 0; k0 < INF; k0 += 16) {
        #pragma unroll
        for (int q = 0; q < 4; q++) {
            int m = q * 16 + (tid >> 4);
            int kk = tid & 15;
            As[m][kk] = p.x[(size_t)(m0 + m) * XROW + 2 + k0 + kk];
        }
        {
            int idx = tid * 4;
            int kk = idx >> 6;
            int hcq = idx & 63;
            float4 w = *(const float4*)&W[(size_t)(k0 + kk) * HH + n0 + hcq];
            *(float4*)&Bs[kk][hcq] = w;
        }
        __syncthreads();

        #pragma unroll
        for (int kk = 0; kk < 16; kk++) {
            ulonglong2 bq = *(const ulonglong2*)&Bs[kk][tn * 4];
            #pragma unroll
            for (int i = 0; i < 4; i++) {
                float a = As[tm * 4 + i][kk];
                unsigned long long a2 = pk2(a, a);
                fma2(acc2[i][0], a2, bq.x);
                fma2(acc2[i][1], a2, bq.y);
            }
        }
        __syncthreads();
    }

    const float* bias = p.bias[g];
    const float* a1p = p.aux1[g];
    const float* a2p = p.aux2[g];

    #pragma unroll
    for (int i = 0; i < 4; i++) {
        int m = m0 + tm * 4 + i;
        int bidx = m / SS;
        int sidx = m % SS;
        float Tt = p.x[(size_t)m * XROW + 0];
        float Dt = p.x[(size_t)m * XROW + 1];
        size_t base = (((size_t)sidx * 8 + g) * BB + bidx) * HH;
        float2 lo = upk2(acc2[i][0]);
        float2 hi = upk2(acc2[i][1]);
        float av[4] = {lo.x, lo.y, hi.x, hi.y};
        #pragma unroll
        for (int j = 0; j < 4; j++) {
            int h = n0 + tn * 4 + j;
            float v = av[j] + bias[h];
            if (g == 3 || g == 4)       v += sigf(Tt * a1p[h]);
            else if (g == 5 || g == 6)  v += sigf(Dt * a1p[h]);
            else if (g == 7)            v += Tt * a1p[h] + Dt * a2p[h];
            g_G[base + h] = v;
        }
    }
}

// ---------------------------------------------------------------------------
// One-time weight interleave: g_Wint[hblk][k][hc][g] so each step block can
// fetch its whole weight slice with ONE 32KB bulk copy.
// ---------------------------------------------------------------------------
__global__ void winit_kernel(const float* __restrict__ Whi,
                             const float* __restrict__ Whf,
                             const float* __restrict__ Whc,
                             const float* __restrict__ Who) {
    const int hblk = blockIdx.x;
    const int h0 = hblk * 4;
    const float* Wg[4] = {Whi, Whf, Whc, Who};
    for (int idx = threadIdx.x; idx < HH * 16; idx += blockDim.x) {
        int k = idx >> 4, hcc = (idx >> 2) & 3, g = idx & 3;
        g_Wint[(size_t)hblk * (HH * 16) + idx] = Wg[g][(size_t)k * HH + h0 + hcc];
    }
}

// ---------------------------------------------------------------------------
// LAUNCHED per-step kernel. 128 blocks x 512 threads. R13 mainloop body,
// but h chunks + weights arrive via cp.async.bulk (8+1 instructions/step
// instead of 32K+2K LDGSTS — the measured LDGSTS-issue wall of R3-R13).
// ---------------------------------------------------------------------------
__global__ void __launch_bounds__(512, 1)
step_kernel(float* __restrict__ out, unsigned long long out_size, int t) {
    extern __shared__ __align__(16) char smem_raw[];
    float* wsf   = (float*)(smem_raw + SM_WS);   // [k][hc][g: i,f,c,o]
    float* Asmem = (float*)(smem_raw + SM_AS);   // 2 x [KC][256]
    float* Gs    = (float*)(smem_raw + SM_GS);   // [g][b][4h]
    const unsigned mbW = smem_u32(smem_raw + SM_MB);
    const unsigned mb0 = smem_u32(smem_raw + SM_MB + 8);
    const unsigned mb1 = smem_u32(smem_raw + SM_MB + 16);
    const unsigned wsAddr = smem_u32(wsf);
    const unsigned aAddr  = smem_u32(Asmem);

    const int tid = threadIdx.x;
    const int h0 = blockIdx.x * 4;
    const int hc = tid & 3;
    const int b0 = (tid >> 2) * 2;

    const float* hT = g_hT[t & 1];
    float* hTn = g_hT[(t + 1) & 1];

    if (tid == 0) {
        mbar_init(mbW, 1);
        mbar_init(mb0, 1);
        mbar_init(mb1, 1);
        asm volatile("fence.proxy.async;" ::: "memory");
    }
    __syncthreads();

    // G slices via cp.async (overlapped with mainloop; epilogue-only data)
    {
        #pragma unroll
        for (int i = 0; i < 4; i++) {
            int idx = i * 512 + tid;
            int g = idx >> 8, b = idx & 255;
            const float* srcg = g_G + (((size_t)t * 8 + g) * BB + b) * HH + h0;
            cpa16(Gs + (size_t)idx * 4, srcg);
        }
        CP_COMMIT();
    }

    // Bulk copies: weights (32KB) + h chunks 0,1 (64KB each)
    if (t > 0 && tid == 0) {
        mbar_expect_tx(mbW, WSB);
        bulk_g2s(wsAddr, g_Wint + (size_t)blockIdx.x * (HH * 16), WSB, mbW);
        mbar_expect_tx(mb0, CHB);
        bulk_g2s(aAddr, hT, CHB, mb0);
        mbar_expect_tx(mb1, CHB);
        bulk_g2s(aAddr + CHB, (const char*)hT + CHB, CHB, mb1);
    }

    // cell state: (h0+hc, b0..b0+1)
    float cst[2] = {0.f, 0.f};
    if (t > 0) {
        float2 cv = __ldcg((const float2*)&g_c[(h0 + hc) * BB + b0]);
        cst[0] = cv.x; cst[1] = cv.y;
    }

    unsigned long long accIF[2] = {0ULL, 0ULL};
    unsigned long long accCO[2] = {0ULL, 0ULL};

    if (t > 0) {
        int ph0 = 0, ph1 = 0;
        mbar_wait(mbW, 0);
        for (int c = 0; c < NCHUNK; c++) {
            if ((c & 1) == 0) { mbar_wait(mb0, ph0); ph0 ^= 1; }
            else              { mbar_wait(mb1, ph1); ph1 ^= 1; }

            const float* A = Asmem + (size_t)(c & 1) * (KC * 256) + b0;
            const float* wp = wsf + ((size_t)c * KC * 4 + hc) * 4;
            #pragma unroll 8
            for (int k = 0; k < KC; k++) {
                float2 av = *(const float2*)(A + k * 256);
                ulonglong2 w = *(const ulonglong2*)(wp + (size_t)k * 16);
                unsigned long long a0 = pk2(av.x, av.x);
                unsigned long long a1 = pk2(av.y, av.y);
                fma2(accIF[0], a0, w.x);
                fma2(accCO[0], a0, w.y);
                fma2(accIF[1], a1, w.x);
                fma2(accCO[1], a1, w.y);
            }
            __syncthreads();   // all readers done with buffer (c&1)
            if (tid == 0 && c + 2 < NCHUNK) {
                unsigned mb = (c & 1) ? mb1 : mb0;
                mbar_expect_tx(mb, CHB);
                bulk_g2s(aAddr + (unsigned)(c & 1) * CHB,
                         (const char*)hT + (size_t)(c + 2) * CHB, CHB, mb);
            }
        }
    }

    CP_WAIT(0);        // own G cp.async ops done
    __syncthreads();   // everyone's G slices visible

    float hn[2];
    #pragma unroll
    for (int r = 0; r < 2; r++) {
        int b = b0 + r;
        float2 yif = upk2(accIF[r]);
        float2 yco = upk2(accCO[r]);
        float xi = Gs[(0 * 256 + b) * 4 + hc] + yif.x;
        float xf = Gs[(1 * 256 + b) * 4 + hc] + yif.y;
        float xc = Gs[(2 * 256 + b) * 4 + hc] + yco.x;
        float t1 = Gs[(3 * 256 + b) * 4 + hc];
        float t2 = Gs[(4 * 256 + b) * 4 + hc];
        float d1 = Gs[(5 * 256 + b) * 4 + hc];
        float d2 = Gs[(6 * 256 + b) * 4 + hc];
        float o  = Gs[(7 * 256 + b) * 4 + hc] + yco.y;

        float it = sigf(xi);
        float ft = sigf(xf);
        float jj = tanh_fast(xc);
        float T1 = sigf(t1), T2 = sigf(t2), D1 = sigf(d1), D2 = sigf(d2);
        float fc = ft * cst[r];
        float ij = it * jj;
        float chat = fc + ij * T1 * D1;
        float cnew = fc + ij * T2 * D2;
        float ot = sigf(o);
        hn[r] = ot * tanh_fast(chat);
        cst[r] = cnew;
    }

    // next-step hidden + cell state: [h][b] layout, float2 over b
    *(float2*)&hTn[(h0 + hc) * BB + b0] = make_float2(hn[0], hn[1]);
    *(float2*)&g_c[(h0 + hc) * BB + b0] = make_float2(cst[0], cst[1]);

    // stage hn (and c at last step) so 256 threads emit ONE STG.128 each
    float* hs = Asmem;
    float* cs = Asmem + 4096;
    #pragma unroll
    for (int r = 0; r < 2; r++) hs[(b0 + r) * 4 + hc] = hn[r];
    if (t == SS - 1) {
        #pragma unroll
        for (int r = 0; r < 2; r++) cs[(b0 + r) * 4 + hc] = cst[r];
    }
    __syncthreads();
    if (tid < BB) {
        float4 v = *(const float4*)&hs[tid * 4];
        *(float4*)&out[((size_t)tid * SS + t) * HH + h0] = v;
        if (t == SS - 1) {
            unsigned long long base = (unsigned long long)BB * SS * HH;
            unsigned long long o1 = base + (unsigned long long)tid * HH + h0;
            unsigned long long o2 = o1 + (unsigned long long)BB * HH;
            if (o1 + 4 <= out_size) *(float4*)&out[o1] = v;
            if (o2 + 4 <= out_size) *(float4*)&out[o2] = *(const float4*)&cs[tid * 4];
        }
    }
}

extern "C" void kernel_launch(void* const* d_in, const int* in_sizes, int n_in,
                              void* d_out, int out_size) {
    const float* x = (const float*)d_in[0];

    ProjArgs pa = {};
    pa.x = x;
    pa.Wx[0] = (const float*)d_in[1];  pa.bias[0] = (const float*)d_in[3];
    pa.Wx[1] = (const float*)d_in[4];  pa.bias[1] = (const float*)d_in[6];
    pa.Wx[2] = (const float*)d_in[7];  pa.bias[2] = (const float*)d_in[9];
    pa.Wx[3] = (const float*)d_in[10]; pa.aux1[3] = (const float*)d_in[11]; pa.bias[3] = (const float*)d_in[12];
    pa.Wx[4] = (const float*)d_in[13]; pa.aux1[4] = (const float*)d_in[14]; pa.bias[4] = (const float*)d_in[15];
    pa.Wx[5] = (const float*)d_in[16]; pa.aux1[5] = (const float*)d_in[17]; pa.bias[5] = (const float*)d_in[18];
    pa.Wx[6] = (const float*)d_in[19]; pa.aux1[6] = (const float*)d_in[20]; pa.bias[6] = (const float*)d_in[21];
    pa.Wx[7] = (const float*)d_in[22]; pa.aux1[7] = (const float*)d_in[24]; pa.aux2[7] = (const float*)d_in[25];
    pa.bias[7] = (const float*)d_in[26];

    const float* Whi = (const float*)d_in[2];
    const float* Whf = (const float*)d_in[5];
    const float* Whc = (const float*)d_in[8];
    const float* Who = (const float*)d_in[23];

    float* out = (float*)d_out;

    cudaFuncSetAttribute(step_kernel, cudaFuncAttributeMaxDynamicSharedMemorySize,
                         SM_TOTAL);

    dim3 pgrid(HH / 64, (BB * SS) / 64, 8);
    proj_kernel<<<pgrid, 256>>>(pa);

    winit_kernel<<<NBLK, 256>>>(Whi, Whf, Whc, Who);

    for (int t = 0; t < SS; t++) {
        step_kernel<<<NBLK, 512, SM_TOTAL>>>(out, (unsigned long long)out_size, t);
    }
}